// round 1
// baseline (speedup 1.0000x reference)
#include <cuda_runtime.h>
#include <cstdint>
#include <math.h>

// ---------------------------------------------------------------------------
// MinGRUCell: g = sigmoid(x Wg^T + bg), c = tanh(x Wh^T + bh)
//             h_t = g_t * h_{t-1} + (1-g_t) * c_t   (scan along L), h_0 = hidden
// Shapes: x (B,L,D) = (8,4096,1024) fp32; Wg/Wh (D,D); bg/bh (D); out (B,L,D)
// Plan:
//   K1: tf32 tensor-core GEMM (M=32768, N=1024, K=1024), gridDim.z selects
//       (Wg,bg,sigmoid->g_gate) vs (Wh,bh,tanh->g_cand).
//   K2..K4: chunked affine scan: per-chunk composites, serial chunk prefix,
//       apply prefix + write h.
// ---------------------------------------------------------------------------

constexpr int B_  = 8;
constexpr int L_  = 4096;
constexpr int D_  = 1024;
constexpr int M_  = B_ * L_;       // 32768
constexpr int Ksz = D_;
constexpr int Nsz = D_;

constexpr int BM = 128, BN = 128, BK = 16;
constexpr int NKT = Ksz / BK;      // 64 k-tiles
constexpr int PAD = 4;

constexpr int NC = 64;             // scan chunks along L
constexpr int CL = L_ / NC;        // 64 steps per chunk

// Scratch (device globals: allocation-free per harness rules)
__device__ float g_gate[(size_t)M_ * D_];       // sigmoid(x Wg^T + bg)
__device__ float g_cand[(size_t)M_ * D_];       // tanh(x Wh^T + bh)
__device__ float g_Ac [B_ * NC * D_];           // per-chunk composite A
__device__ float g_Bc [B_ * NC * D_];           // per-chunk composite B
__device__ float g_hin[B_ * NC * D_];           // h entering each chunk

static __device__ __forceinline__ uint32_t f2tf32(float f) {
    uint32_t r;
    asm("cvt.rna.tf32.f32 %0, %1;" : "=r"(r) : "f"(f));
    return r;
}

static __device__ __forceinline__ void mma8(float* c, const uint32_t* a, const uint32_t* b) {
    asm volatile(
        "mma.sync.aligned.m16n8k8.row.col.f32.tf32.tf32.f32 "
        "{%0,%1,%2,%3}, {%4,%5,%6,%7}, {%8,%9}, {%0,%1,%2,%3};\n"
        : "+f"(c[0]), "+f"(c[1]), "+f"(c[2]), "+f"(c[3])
        : "r"(a[0]), "r"(a[1]), "r"(a[2]), "r"(a[3]),
          "r"(b[0]), "r"(b[1]));
}

// ---------------------------------------------------------------------------
// K1: tiled tf32 GEMM + bias + activation.
// C[m][n] = sum_k x[m][k] * W[n][k]  (both K-contiguous, NT layout)
// Block: 256 thr (8 warps, 2x4), tile 128x128, BK=16, double-buffered smem.
// Warp tile 64x32 -> 4x4 m16n8 mma tiles, 64 fp32 accum/thread.
// ---------------------------------------------------------------------------
__global__ void __launch_bounds__(256) gemm_act_kernel(
    const float* __restrict__ x,
    const float* __restrict__ Wg, const float* __restrict__ bg,
    const float* __restrict__ Wh, const float* __restrict__ bh)
{
    const int zi = blockIdx.z;
    const float* __restrict__ Wm   = zi ? Wh : Wg;
    const float* __restrict__ bias = zi ? bh : bg;
    float* __restrict__ outp       = zi ? g_cand : g_gate;

    __shared__ uint32_t As[2][BK][BM + PAD];
    __shared__ uint32_t Bs[2][BK][BN + PAD];

    const int tid  = threadIdx.x;
    const int m0   = blockIdx.y * BM;
    const int n0   = blockIdx.x * BN;
    const int warp = tid >> 5, lane = tid & 31;
    const int g    = lane >> 2;        // 0..7
    const int tg   = lane & 3;         // 0..3
    const int wm   = (warp >> 2) * 64; // 0 / 64
    const int wn   = (warp & 3) * 32;  // 0..96

    float acc[4][4][4];
#pragma unroll
    for (int i = 0; i < 4; i++)
#pragma unroll
        for (int j = 0; j < 4; j++)
#pragma unroll
            for (int r = 0; r < 4; r++) acc[i][j][r] = 0.f;

    float4 ra[2], rb[2];

    auto ldg_stage = [&](int kt) {
#pragma unroll
        for (int s = 0; s < 2; s++) {
            int gi = tid + s * 256;
            int row = gi >> 2, kq = (gi & 3) * 4;
            ra[s] = *(const float4*)(x  + (size_t)(m0 + row) * Ksz + kt * BK + kq);
            rb[s] = *(const float4*)(Wm + (size_t)(n0 + row) * Ksz + kt * BK + kq);
        }
    };
    auto sts_stage = [&](int buf) {
#pragma unroll
        for (int s = 0; s < 2; s++) {
            int gi = tid + s * 256;
            int row = gi >> 2, kq = (gi & 3) * 4;
            As[buf][kq + 0][row] = f2tf32(ra[s].x);
            As[buf][kq + 1][row] = f2tf32(ra[s].y);
            As[buf][kq + 2][row] = f2tf32(ra[s].z);
            As[buf][kq + 3][row] = f2tf32(ra[s].w);
            Bs[buf][kq + 0][row] = f2tf32(rb[s].x);
            Bs[buf][kq + 1][row] = f2tf32(rb[s].y);
            Bs[buf][kq + 2][row] = f2tf32(rb[s].z);
            Bs[buf][kq + 3][row] = f2tf32(rb[s].w);
        }
    };
    auto compute = [&](int buf) {
#pragma unroll
        for (int k8 = 0; k8 < BK; k8 += 8) {
            uint32_t af[4][4], bf[4][2];
#pragma unroll
            for (int mt = 0; mt < 4; mt++) {
                int m = wm + mt * 16 + g;
                af[mt][0] = As[buf][k8 + tg    ][m];
                af[mt][1] = As[buf][k8 + tg    ][m + 8];
                af[mt][2] = As[buf][k8 + tg + 4][m];
                af[mt][3] = As[buf][k8 + tg + 4][m + 8];
            }
#pragma unroll
            for (int nt = 0; nt < 4; nt++) {
                int n = wn + nt * 8 + g;
                bf[nt][0] = Bs[buf][k8 + tg    ][n];
                bf[nt][1] = Bs[buf][k8 + tg + 4][n];
            }
#pragma unroll
            for (int mt = 0; mt < 4; mt++)
#pragma unroll
                for (int nt = 0; nt < 4; nt++)
                    mma8(acc[mt][nt], af[mt], bf[nt]);
        }
    };

    ldg_stage(0);
    sts_stage(0);
    __syncthreads();
    for (int kt = 0; kt < NKT; kt++) {
        int buf = kt & 1;
        if (kt + 1 < NKT) ldg_stage(kt + 1);
        compute(buf);
        if (kt + 1 < NKT) {
            sts_stage(buf ^ 1);
            __syncthreads();
        }
    }

    // Epilogue: bias + activation + store
    float bcol[8];
#pragma unroll
    for (int nt = 0; nt < 4; nt++) {
        int col = n0 + wn + nt * 8 + tg * 2;
        bcol[nt * 2]     = bias[col];
        bcol[nt * 2 + 1] = bias[col + 1];
    }
#pragma unroll
    for (int mt = 0; mt < 4; mt++) {
#pragma unroll
        for (int nt = 0; nt < 4; nt++) {
            int row = m0 + wm + mt * 16 + g;
            int col = n0 + wn + nt * 8 + tg * 2;
#pragma unroll
            for (int h = 0; h < 2; h++) {
                int r = row + h * 8;
                float z0 = acc[mt][nt][h * 2 + 0] + bcol[nt * 2];
                float z1 = acc[mt][nt][h * 2 + 1] + bcol[nt * 2 + 1];
                float v0, v1;
                if (zi == 0) {
                    v0 = 1.f / (1.f + expf(-z0));
                    v1 = 1.f / (1.f + expf(-z1));
                } else {
                    v0 = tanhf(z0);
                    v1 = tanhf(z1);
                }
                *(float2*)(outp + (size_t)r * Nsz + col) = make_float2(v0, v1);
            }
        }
    }
}

// ---------------------------------------------------------------------------
// K2: per-chunk affine composites. h_out = A*h_in + B with
//     A = prod a_l, B = recurrence from 0; a = g, b = (1-g)*c.
// Grid (NC, B), 256 thr; thread t owns d = 4t..4t+3 (float4, coalesced).
// ---------------------------------------------------------------------------
__global__ void __launch_bounds__(256) scan_phase1()
{
    const int b = blockIdx.y, ch = blockIdx.x;
    const int d4 = threadIdx.x;
    const size_t base = ((size_t)(b * L_ + ch * CL) * D_) / 4 + d4;
    const float4* __restrict__ gp = (const float4*)g_gate + base;
    const float4* __restrict__ cp = (const float4*)g_cand + base;

    float4 A  = make_float4(1.f, 1.f, 1.f, 1.f);
    float4 Bv = make_float4(0.f, 0.f, 0.f, 0.f);
#pragma unroll 4
    for (int l = 0; l < CL; l++) {
        float4 gv = gp[(size_t)l * (D_ / 4)];
        float4 cv = cp[(size_t)l * (D_ / 4)];
        Bv.x = gv.x * Bv.x + (1.f - gv.x) * cv.x;  A.x *= gv.x;
        Bv.y = gv.y * Bv.y + (1.f - gv.y) * cv.y;  A.y *= gv.y;
        Bv.z = gv.z * Bv.z + (1.f - gv.z) * cv.z;  A.z *= gv.z;
        Bv.w = gv.w * Bv.w + (1.f - gv.w) * cv.w;  A.w *= gv.w;
    }
    const size_t o = ((size_t)(b * NC + ch) * D_) / 4 + d4;
    ((float4*)g_Ac)[o] = A;
    ((float4*)g_Bc)[o] = Bv;
}

// ---------------------------------------------------------------------------
// K3: serial prefix across NC chunks per channel (B*D = 8192 threads).
// ---------------------------------------------------------------------------
__global__ void __launch_bounds__(256) scan_phase2(const float* __restrict__ hidden)
{
    const int idx = blockIdx.x * blockDim.x + threadIdx.x;   // 0..8191
    const int b = idx >> 10, d = idx & (D_ - 1);
    float h = hidden[idx];
#pragma unroll 8
    for (int c = 0; c < NC; c++) {
        const size_t o = (size_t)(b * NC + c) * D_ + d;
        g_hin[o] = h;
        h = g_Ac[o] * h + g_Bc[o];
    }
}

// ---------------------------------------------------------------------------
// K4: apply per-chunk entering state, emit h_t.
// ---------------------------------------------------------------------------
__global__ void __launch_bounds__(256) scan_phase3(float* __restrict__ out)
{
    const int b = blockIdx.y, ch = blockIdx.x;
    const int d4 = threadIdx.x;
    const size_t base = ((size_t)(b * L_ + ch * CL) * D_) / 4 + d4;
    const float4* __restrict__ gp = (const float4*)g_gate + base;
    const float4* __restrict__ cp = (const float4*)g_cand + base;
    float4* __restrict__ op = (float4*)out + base;

    float4 h = ((const float4*)g_hin)[((size_t)(b * NC + ch) * D_) / 4 + d4];
#pragma unroll 4
    for (int l = 0; l < CL; l++) {
        float4 gv = gp[(size_t)l * (D_ / 4)];
        float4 cv = cp[(size_t)l * (D_ / 4)];
        h.x = gv.x * h.x + (1.f - gv.x) * cv.x;
        h.y = gv.y * h.y + (1.f - gv.y) * cv.y;
        h.z = gv.z * h.z + (1.f - gv.z) * cv.z;
        h.w = gv.w * h.w + (1.f - gv.w) * cv.w;
        op[(size_t)l * (D_ / 4)] = h;
    }
}

// ---------------------------------------------------------------------------
extern "C" void kernel_launch(void* const* d_in, const int* in_sizes, int n_in,
                              void* d_out, int out_size)
{
    const float* x      = (const float*)d_in[0];
    const float* hidden = (const float*)d_in[1];
    const float* Wg     = (const float*)d_in[2];
    const float* bg     = (const float*)d_in[3];
    const float* Wh     = (const float*)d_in[4];
    const float* bh     = (const float*)d_in[5];
    float* out = (float*)d_out;

    dim3 gg(Nsz / BN, M_ / BM, 2);        // (8, 256, 2)
    gemm_act_kernel<<<gg, 256>>>(x, Wg, bg, Wh, bh);

    scan_phase1<<<dim3(NC, B_), 256>>>();
    scan_phase2<<<(B_ * D_) / 256, 256>>>(hidden);
    scan_phase3<<<dim3(NC, B_), 256>>>(out);
}

// round 6
// speedup vs baseline: 1.9719x; 1.9719x over previous
#include <cuda_runtime.h>
#include <cuda_fp16.h>
#include <cstdint>
#include <math.h>

// ---------------------------------------------------------------------------
// MinGRUCell on GB300 (sm_103a) — Round 6.
// tcgen05 is unavailable (harness compiles PTX at compute_103, not 103a), so
// use the legacy mma.sync pipe at its fastest usable dtype: fp16 (m16n8k16,
// fp32 accumulate). fp16 mantissa (10b) == tf32 mantissa, so accuracy matches
// the passing tf32 kernel (~3.6e-4), at (expected) 2x the tensor rate.
//   g = sigmoid(x Wg^T + bg), c = tanh(x Wh^T + bh)
//   h_t = g h_{t-1} + (1-g) c   (chunked affine scan along L)
// ---------------------------------------------------------------------------

constexpr int B_  = 8;
constexpr int L_  = 4096;
constexpr int D_  = 1024;
constexpr int M_  = B_ * L_;     // 32768
constexpr int Ksz = D_;
constexpr int Nsz = D_;

constexpr int BM = 128, BN = 128, BK = 32;   // BK in K-elements (16 half2)
constexpr int NKT = Ksz / BK;                // 32 k-tiles
constexpr int SROW = 20;                     // row stride in words (16 + 4 pad)
// LDS banks: addr = m*20 + tg -> 20*m mod 32 = {0,20,8,28,16,4,24,12}: all 32
// lanes (8 m x 4 tg) hit distinct banks. Conflict-free fragment loads.

constexpr int NC = 64;           // scan chunks
constexpr int CL = L_ / NC;      // 64

// Scratch
__device__ float g_gate[(size_t)M_ * D_];
__device__ float g_cand[(size_t)M_ * D_];
__device__ float g_Ac [B_ * NC * D_];
__device__ float g_Bc [B_ * NC * D_];
__device__ float g_hin[B_ * NC * D_];

static __device__ __forceinline__ uint32_t pack2(float a, float b) {
    // half2(lo=a, hi=b), round-to-nearest-even
    __half2 h = __floats2half2_rn(a, b);
    return *reinterpret_cast<uint32_t*>(&h);
}

static __device__ __forceinline__ void mma16(float* c, const uint32_t* a, const uint32_t* b) {
    asm volatile(
        "mma.sync.aligned.m16n8k16.row.col.f32.f16.f16.f32 "
        "{%0,%1,%2,%3}, {%4,%5,%6,%7}, {%8,%9}, {%0,%1,%2,%3};\n"
        : "+f"(c[0]), "+f"(c[1]), "+f"(c[2]), "+f"(c[3])
        : "r"(a[0]), "r"(a[1]), "r"(a[2]), "r"(a[3]),
          "r"(b[0]), "r"(b[1]));
}

// ---------------------------------------------------------------------------
// K1: tiled fp16 GEMM + bias + activation.
// C[m][n] = sum_k x[m][k] * W[n][k]  (NT). grid.z: 0 = gate, 1 = cand.
// Block 256 thr (8 warps, 2x4), tile 128x128, BK=32, double-buffered SMEM.
// Warp tile 64x32 -> 4x4 m16n8 tiles, 2 k16 steps per k-tile.
// ---------------------------------------------------------------------------
__global__ void __launch_bounds__(256) gemm_act_fp16(
    const float* __restrict__ x,
    const float* __restrict__ Wg, const float* __restrict__ bg,
    const float* __restrict__ Wh, const float* __restrict__ bh)
{
    const int zi = blockIdx.z;
    const float* __restrict__ Wm   = zi ? Wh : Wg;
    const float* __restrict__ bias = zi ? bh : bg;
    float* __restrict__ outp       = zi ? g_cand : g_gate;

    // [buf][row][k2], k2 in 0..15 (half2 index), padded row stride 20 words
    __shared__ uint32_t As[2][BM][SROW];
    __shared__ uint32_t Bs[2][BN][SROW];

    const int tid  = threadIdx.x;
    const int m0   = blockIdx.y * BM;
    const int n0   = blockIdx.x * BN;
    const int warp = tid >> 5, lane = tid & 31;
    const int g    = lane >> 2;        // 0..7
    const int tg   = lane & 3;         // 0..3
    const int wm   = (warp >> 2) * 64; // 0 / 64
    const int wn   = (warp & 3) * 32;  // 0..96

    float acc[4][4][4];
#pragma unroll
    for (int i = 0; i < 4; i++)
#pragma unroll
        for (int j = 0; j < 4; j++)
#pragma unroll
            for (int r = 0; r < 4; r++) acc[i][j][r] = 0.f;

    // Per stage: A tile 128x32 floats = 1024 float4; 256 thr -> 4 each. Same B.
    float4 ra[4], rb[4];

    auto ldg_stage = [&](int kt) {
#pragma unroll
        for (int i = 0; i < 4; i++) {
            const int f   = tid + i * 256;     // 0..1023
            const int row = f >> 3;            // 0..127
            const int q   = f & 7;             // float4 within row
            ra[i] = *(const float4*)(x  + (size_t)(m0 + row) * Ksz + kt * BK + q * 4);
            rb[i] = *(const float4*)(Wm + (size_t)(n0 + row) * Ksz + kt * BK + q * 4);
        }
    };
    auto sts_stage = [&](int buf) {
#pragma unroll
        for (int i = 0; i < 4; i++) {
            const int f   = tid + i * 256;
            const int row = f >> 3;
            const int q   = f & 7;
            uint32_t a0 = pack2(ra[i].x, ra[i].y);
            uint32_t a1 = pack2(ra[i].z, ra[i].w);
            uint32_t b0 = pack2(rb[i].x, rb[i].y);
            uint32_t b1 = pack2(rb[i].z, rb[i].w);
            *(uint2*)&As[buf][row][2 * q] = make_uint2(a0, a1);
            *(uint2*)&Bs[buf][row][2 * q] = make_uint2(b0, b1);
        }
    };
    auto compute = [&](int buf) {
#pragma unroll
        for (int ks = 0; ks < 2; ks++) {       // two k16 steps per k-tile
            const int kb = ks * 8;
            uint32_t af[4][4], bf[4][2];
#pragma unroll
            for (int mt = 0; mt < 4; mt++) {
                const int m = wm + mt * 16 + g;
                af[mt][0] = As[buf][m    ][kb + tg];
                af[mt][1] = As[buf][m + 8][kb + tg];
                af[mt][2] = As[buf][m    ][kb + 4 + tg];
                af[mt][3] = As[buf][m + 8][kb + 4 + tg];
            }
#pragma unroll
            for (int nt = 0; nt < 4; nt++) {
                const int n = wn + nt * 8 + g;
                bf[nt][0] = Bs[buf][n][kb + tg];
                bf[nt][1] = Bs[buf][n][kb + 4 + tg];
            }
#pragma unroll
            for (int mt = 0; mt < 4; mt++)
#pragma unroll
                for (int nt = 0; nt < 4; nt++)
                    mma16(acc[mt][nt], af[mt], bf[nt]);
        }
    };

    ldg_stage(0);
    sts_stage(0);
    __syncthreads();
    for (int kt = 0; kt < NKT; kt++) {
        const int buf = kt & 1;
        if (kt + 1 < NKT) ldg_stage(kt + 1);
        compute(buf);
        if (kt + 1 < NKT) {
            __syncthreads();            // compute done reading buf^1's next slot
            sts_stage(buf ^ 1);
            __syncthreads();
        }
    }

    // Epilogue: bias + activation + store (fp32 accumulators).
    float bcol[8];
#pragma unroll
    for (int nt = 0; nt < 4; nt++) {
        const int col = n0 + wn + nt * 8 + tg * 2;
        bcol[nt * 2]     = bias[col];
        bcol[nt * 2 + 1] = bias[col + 1];
    }
#pragma unroll
    for (int mt = 0; mt < 4; mt++) {
#pragma unroll
        for (int nt = 0; nt < 4; nt++) {
            const int row = m0 + wm + mt * 16 + g;
            const int col = n0 + wn + nt * 8 + tg * 2;
#pragma unroll
            for (int h = 0; h < 2; h++) {
                const int r = row + h * 8;
                float z0 = acc[mt][nt][h * 2 + 0] + bcol[nt * 2];
                float z1 = acc[mt][nt][h * 2 + 1] + bcol[nt * 2 + 1];
                float v0, v1;
                if (zi == 0) {
                    v0 = 1.f / (1.f + expf(-z0));
                    v1 = 1.f / (1.f + expf(-z1));
                } else {
                    v0 = tanhf(z0);
                    v1 = tanhf(z1);
                }
                *(float2*)(outp + (size_t)r * Nsz + col) = make_float2(v0, v1);
            }
        }
    }
}

// ---------------------------------------------------------------------------
// Scan kernels (phase3 measured at 80.6% DRAM / 6.4 TB/s — near roofline).
// ---------------------------------------------------------------------------
__global__ void __launch_bounds__(256) scan_phase1()
{
    const int b = blockIdx.y, ch = blockIdx.x;
    const int d4 = threadIdx.x;
    const size_t base = ((size_t)(b * L_ + ch * CL) * D_) / 4 + d4;
    const float4* __restrict__ gp = (const float4*)g_gate + base;
    const float4* __restrict__ cp = (const float4*)g_cand + base;

    float4 A  = make_float4(1.f, 1.f, 1.f, 1.f);
    float4 Bv = make_float4(0.f, 0.f, 0.f, 0.f);
#pragma unroll 4
    for (int l = 0; l < CL; l++) {
        float4 gv = gp[(size_t)l * (D_ / 4)];
        float4 cv = cp[(size_t)l * (D_ / 4)];
        Bv.x = gv.x * Bv.x + (1.f - gv.x) * cv.x;  A.x *= gv.x;
        Bv.y = gv.y * Bv.y + (1.f - gv.y) * cv.y;  A.y *= gv.y;
        Bv.z = gv.z * Bv.z + (1.f - gv.z) * cv.z;  A.z *= gv.z;
        Bv.w = gv.w * Bv.w + (1.f - gv.w) * cv.w;  A.w *= gv.w;
    }
    const size_t o = ((size_t)(b * NC + ch) * D_) / 4 + d4;
    ((float4*)g_Ac)[o] = A;
    ((float4*)g_Bc)[o] = Bv;
}

__global__ void __launch_bounds__(256) scan_phase2(const float* __restrict__ hidden)
{
    const int idx = blockIdx.x * blockDim.x + threadIdx.x;   // 0..8191
    const int b = idx >> 10, d = idx & (D_ - 1);
    float h = hidden[idx];
#pragma unroll 8
    for (int c = 0; c < NC; c++) {
        const size_t o = (size_t)(b * NC + c) * D_ + d;
        g_hin[o] = h;
        h = g_Ac[o] * h + g_Bc[o];
    }
}

__global__ void __launch_bounds__(256) scan_phase3(float* __restrict__ out)
{
    const int b = blockIdx.y, ch = blockIdx.x;
    const int d4 = threadIdx.x;
    const size_t base = ((size_t)(b * L_ + ch * CL) * D_) / 4 + d4;
    const float4* __restrict__ gp = (const float4*)g_gate + base;
    const float4* __restrict__ cp = (const float4*)g_cand + base;
    float4* __restrict__ op = (float4*)out + base;

    float4 h = ((const float4*)g_hin)[((size_t)(b * NC + ch) * D_) / 4 + d4];
#pragma unroll 4
    for (int l = 0; l < CL; l++) {
        float4 gv = gp[(size_t)l * (D_ / 4)];
        float4 cv = cp[(size_t)l * (D_ / 4)];
        h.x = gv.x * h.x + (1.f - gv.x) * cv.x;
        h.y = gv.y * h.y + (1.f - gv.y) * cv.y;
        h.z = gv.z * h.z + (1.f - gv.z) * cv.z;
        h.w = gv.w * h.w + (1.f - gv.w) * cv.w;
        op[(size_t)l * (D_ / 4)] = h;
    }
}

// ---------------------------------------------------------------------------
extern "C" void kernel_launch(void* const* d_in, const int* in_sizes, int n_in,
                              void* d_out, int out_size)
{
    const float* x      = (const float*)d_in[0];
    const float* hidden = (const float*)d_in[1];
    const float* Wg     = (const float*)d_in[2];
    const float* bg     = (const float*)d_in[3];
    const float* Wh     = (const float*)d_in[4];
    const float* bh     = (const float*)d_in[5];
    float* out = (float*)d_out;

    gemm_act_fp16<<<dim3(Nsz / BN, M_ / BM, 2), 256>>>(x, Wg, bg, Wh, bh);

    scan_phase1<<<dim3(NC, B_), 256>>>();
    scan_phase2<<<(B_ * D_) / 256, 256>>>(hidden);
    scan_phase3<<<dim3(NC, B_), 256>>>(out);
}

// round 11
// speedup vs baseline: 2.8476x; 1.4441x over previous
#include <cuda_runtime.h>
#include <cuda_fp16.h>
#include <cstdint>
#include <math.h>

// ---------------------------------------------------------------------------
// MinGRUCell on GB300 (sm_103a) — Round 8 (R7 resubmit, rules-clean).
//   g = sigmoid(x Wg^T + bg), c = tanh(x Wh^T + bh)
//   h_t = g h_{t-1} + (1-g) c   (chunked affine scan along L)
// GEMM path (legacy mma.sync pipe; tcgen05 unavailable at compute_103):
//   P0: convert x/Wg/Wh to fp16 in global scratch (rn — same error model).
//   K1: fp16 m16n8k16 GEMM with cp.async 3-stage pipeline + ldmatrix.x4
//       fragments + fused bias/activation epilogue.
//   K2-K4: chunked affine scan (phase3 measured 80.9% DRAM — near roofline).
// Rules note: no statics in kernel_launch; cudaFuncSetAttribute called
// unconditionally (idempotent, capture-safe).
// ---------------------------------------------------------------------------

constexpr int B_  = 8;
constexpr int L_  = 4096;
constexpr int D_  = 1024;
constexpr int M_  = B_ * L_;     // 32768
constexpr int Nsz = D_;

constexpr int BM = 128, BN = 128;
constexpr int BKH   = 64;            // K per tile in halves (= 128 B rows)
constexpr int NKT   = D_ / BKH;      // 16
constexpr int STAGES = 3;
constexpr int TILE_B  = 128 * 128;   // one operand tile: 128 rows x 128 B = 16 KB
constexpr int STAGE_B = 2 * TILE_B;  // A + B
constexpr int DYN_SMEM = STAGES * STAGE_B;   // 96 KB

constexpr int NC = 64;           // scan chunks
constexpr int CL = L_ / NC;      // 64

// Scratch
__device__ __half g_xh[(size_t)M_ * D_];        // x in fp16
__device__ __half g_wh[2 * (size_t)D_ * D_];    // [Wg | Wh] in fp16
__device__ float  g_gate[(size_t)M_ * D_];
__device__ float  g_cand[(size_t)M_ * D_];
__device__ float  g_Ac [B_ * NC * D_];
__device__ float  g_Bc [B_ * NC * D_];
__device__ float  g_hin[B_ * NC * D_];

// ---------------------------------------------------------------------------
// helpers
// ---------------------------------------------------------------------------
static __device__ __forceinline__ uint32_t smem_u32(const void* p) {
    uint32_t a;
    asm("{ .reg .u64 t; cvta.to.shared.u64 t, %1; cvt.u32.u64 %0, t; }" : "=r"(a) : "l"(p));
    return a;
}
static __device__ __forceinline__ void cp16(uint32_t sdst, const void* gsrc) {
    asm volatile("cp.async.cg.shared.global [%0], [%1], 16;"
                 :: "r"(sdst), "l"(__cvta_generic_to_global(gsrc)) : "memory");
}
#define CP_COMMIT() asm volatile("cp.async.commit_group;" ::: "memory")
template <int N>
static __device__ __forceinline__ void cp_wait() {
    asm volatile("cp.async.wait_group %0;" :: "n"(N) : "memory");
}
static __device__ __forceinline__ void ldsm4(uint32_t* r, uint32_t addr) {
    asm volatile("ldmatrix.sync.aligned.m8n8.x4.shared.b16 {%0,%1,%2,%3}, [%4];"
                 : "=r"(r[0]), "=r"(r[1]), "=r"(r[2]), "=r"(r[3]) : "r"(addr));
}
static __device__ __forceinline__ void mma16(float* c, const uint32_t* a, const uint32_t* b) {
    asm volatile(
        "mma.sync.aligned.m16n8k16.row.col.f32.f16.f16.f32 "
        "{%0,%1,%2,%3}, {%4,%5,%6,%7}, {%8,%9}, {%0,%1,%2,%3};\n"
        : "+f"(c[0]), "+f"(c[1]), "+f"(c[2]), "+f"(c[3])
        : "r"(a[0]), "r"(a[1]), "r"(a[2]), "r"(a[3]),
          "r"(b[0]), "r"(b[1]));
}

// ---------------------------------------------------------------------------
// P0: fp32 -> fp16 conversion (8 floats / thread, 16B stores)
// ---------------------------------------------------------------------------
__global__ void __launch_bounds__(256) to_half(const float* __restrict__ src,
                                               __half* __restrict__ dst, int n8)
{
    const int i = blockIdx.x * blockDim.x + threadIdx.x;
    if (i >= n8) return;
    const float4* s = (const float4*)src + 2 * (size_t)i;
    float4 a = s[0], b = s[1];
    __half2 h0 = __floats2half2_rn(a.x, a.y);
    __half2 h1 = __floats2half2_rn(a.z, a.w);
    __half2 h2 = __floats2half2_rn(b.x, b.y);
    __half2 h3 = __floats2half2_rn(b.z, b.w);
    uint4 o = make_uint4(*(uint32_t*)&h0, *(uint32_t*)&h1,
                         *(uint32_t*)&h2, *(uint32_t*)&h3);
    ((uint4*)dst)[i] = o;
}

// ---------------------------------------------------------------------------
// K1: fp16 GEMM, cp.async pipeline + ldmatrix.
// C[m][n] = sum_k xh[m][k] * W[n][k]  (NT). grid.z: 0 = gate, 1 = cand.
// Block 256 (8 warps, 2x4); warp tile 64x32 -> 4x4 m16n8 tiles.
// SMEM tile: 128 rows x 64 halves, 16B-chunk XOR swizzle chunk^=(row&7).
// ---------------------------------------------------------------------------
__global__ void __launch_bounds__(256) gemm_act_fp16(
    const float* __restrict__ bg, const float* __restrict__ bh)
{
    extern __shared__ char dyn[];
    const uint32_t dbase = smem_u32(dyn);

    const int zi = blockIdx.z;
    const __half* __restrict__ Wm = g_wh + (size_t)zi * D_ * D_;
    const float* __restrict__ bias = zi ? bh : bg;
    float* __restrict__ outp = zi ? g_cand : g_gate;

    const int tid  = threadIdx.x;
    const int m0   = blockIdx.y * BM;
    const int n0   = blockIdx.x * BN;
    const int warp = tid >> 5, lane = tid & 31;
    const int g    = lane >> 2;        // 0..7
    const int tg   = lane & 3;         // 0..3
    const int wm   = (warp >> 2) * 64; // 0 / 64
    const int wn   = (warp & 3) * 32;  // 0..96

    const __half* __restrict__ xa = g_xh + (size_t)m0 * D_;
    const __half* __restrict__ wb = Wm   + (size_t)n0 * D_;

    // Fragment ldmatrix lane geometry (x4):
    //   A(mt): row = wm + mt*16 + ((lane>>3)&1)*8 + (lane&7); chunk = ks*2 + (lane>>4)
    //   B(p):  row = wn + p*16  + (lane>>4)*8    + (lane&7); chunk = ks*2 + ((lane>>3)&1)
    const int lrow  = lane & 7;
    const int arow  = ((lane >> 3) & 1) * 8 + lrow;
    const int akadd = lane >> 4;
    const int brow  = (lane >> 4) * 8 + lrow;
    const int bkadd = (lane >> 3) & 1;

    float acc[4][4][4];
#pragma unroll
    for (int i = 0; i < 4; i++)
#pragma unroll
        for (int j = 0; j < 4; j++)
#pragma unroll
            for (int r = 0; r < 4; r++) acc[i][j][r] = 0.f;

    auto load_stage = [&](int stage, int kt) {
        const uint32_t sb = dbase + stage * STAGE_B;
#pragma unroll
        for (int i = 0; i < 4; i++) {
            const int f = tid + i * 256;
            const int row = f >> 3, chunk = f & 7;
            const uint32_t soff = (uint32_t)(row * 128 + ((chunk ^ (row & 7)) << 4));
            const size_t goff = (size_t)row * D_ + kt * BKH + chunk * 8;
            cp16(sb + soff, xa + goff);
            cp16(sb + TILE_B + soff, wb + goff);
        }
    };

    auto compute = [&](int stage) {
        const uint32_t sA = dbase + stage * STAGE_B;
        const uint32_t sB = sA + TILE_B;
#pragma unroll
        for (int ks = 0; ks < 4; ks++) {
            uint32_t af[4][4], bf[4][2];
#pragma unroll
            for (int mt = 0; mt < 4; mt++) {
                const int row = wm + mt * 16 + arow;
                const int ch  = (ks * 2 + akadd) ^ (row & 7);
                ldsm4(af[mt], sA + row * 128 + (ch << 4));
            }
#pragma unroll
            for (int p = 0; p < 2; p++) {
                const int row = wn + p * 16 + brow;
                const int ch  = (ks * 2 + bkadd) ^ (row & 7);
                uint32_t r4[4];
                ldsm4(r4, sB + row * 128 + (ch << 4));
                bf[2 * p][0]     = r4[0];
                bf[2 * p][1]     = r4[1];
                bf[2 * p + 1][0] = r4[2];
                bf[2 * p + 1][1] = r4[3];
            }
#pragma unroll
            for (int mt = 0; mt < 4; mt++)
#pragma unroll
                for (int nt = 0; nt < 4; nt++)
                    mma16(acc[mt][nt], af[mt], bf[nt]);
        }
    };

    // prologue: prefetch stages 0, 1
    load_stage(0, 0); CP_COMMIT();
    load_stage(1, 1); CP_COMMIT();

    for (int kt = 0; kt < NKT; kt++) {
        cp_wait<STAGES - 2>();        // stage kt%STAGES copies complete
        __syncthreads();              // all warps done reading the refill target
        const int pf = kt + STAGES - 1;
        if (pf < NKT) load_stage(pf % STAGES, pf);
        CP_COMMIT();                  // empty commit keeps group accounting aligned
        compute(kt % STAGES);
    }

    // Epilogue: bias + activation + fp32 store
    float bcol[8];
#pragma unroll
    for (int nt = 0; nt < 4; nt++) {
        const int col = n0 + wn + nt * 8 + tg * 2;
        bcol[nt * 2]     = bias[col];
        bcol[nt * 2 + 1] = bias[col + 1];
    }
#pragma unroll
    for (int mt = 0; mt < 4; mt++) {
#pragma unroll
        for (int nt = 0; nt < 4; nt++) {
            const int row = m0 + wm + mt * 16 + g;
            const int col = n0 + wn + nt * 8 + tg * 2;
#pragma unroll
            for (int h = 0; h < 2; h++) {
                const int r = row + h * 8;
                float z0 = acc[mt][nt][h * 2 + 0] + bcol[nt * 2];
                float z1 = acc[mt][nt][h * 2 + 1] + bcol[nt * 2 + 1];
                float v0, v1;
                if (zi == 0) {
                    v0 = 1.f / (1.f + expf(-z0));
                    v1 = 1.f / (1.f + expf(-z1));
                } else {
                    v0 = tanhf(z0);
                    v1 = tanhf(z1);
                }
                *(float2*)(outp + (size_t)r * Nsz + col) = make_float2(v0, v1);
            }
        }
    }
}

// ---------------------------------------------------------------------------
// Scan kernels (phase3: 80.9% DRAM, 6.4 TB/s — near roofline; unchanged).
// ---------------------------------------------------------------------------
__global__ void __launch_bounds__(256) scan_phase1()
{
    const int b = blockIdx.y, ch = blockIdx.x;
    const int d4 = threadIdx.x;
    const size_t base = ((size_t)(b * L_ + ch * CL) * D_) / 4 + d4;
    const float4* __restrict__ gp = (const float4*)g_gate + base;
    const float4* __restrict__ cp = (const float4*)g_cand + base;

    float4 A  = make_float4(1.f, 1.f, 1.f, 1.f);
    float4 Bv = make_float4(0.f, 0.f, 0.f, 0.f);
#pragma unroll 4
    for (int l = 0; l < CL; l++) {
        float4 gv = gp[(size_t)l * (D_ / 4)];
        float4 cv = cp[(size_t)l * (D_ / 4)];
        Bv.x = gv.x * Bv.x + (1.f - gv.x) * cv.x;  A.x *= gv.x;
        Bv.y = gv.y * Bv.y + (1.f - gv.y) * cv.y;  A.y *= gv.y;
        Bv.z = gv.z * Bv.z + (1.f - gv.z) * cv.z;  A.z *= gv.z;
        Bv.w = gv.w * Bv.w + (1.f - gv.w) * cv.w;  A.w *= gv.w;
    }
    const size_t o = ((size_t)(b * NC + ch) * D_) / 4 + d4;
    ((float4*)g_Ac)[o] = A;
    ((float4*)g_Bc)[o] = Bv;
}

__global__ void __launch_bounds__(256) scan_phase2(const float* __restrict__ hidden)
{
    const int idx = blockIdx.x * blockDim.x + threadIdx.x;   // 0..8191
    const int b = idx >> 10, d = idx & (D_ - 1);
    float h = hidden[idx];
#pragma unroll 8
    for (int c = 0; c < NC; c++) {
        const size_t o = (size_t)(b * NC + c) * D_ + d;
        g_hin[o] = h;
        h = g_Ac[o] * h + g_Bc[o];
    }
}

__global__ void __launch_bounds__(256) scan_phase3(float* __restrict__ out)
{
    const int b = blockIdx.y, ch = blockIdx.x;
    const int d4 = threadIdx.x;
    const size_t base = ((size_t)(b * L_ + ch * CL) * D_) / 4 + d4;
    const float4* __restrict__ gp = (const float4*)g_gate + base;
    const float4* __restrict__ cp = (const float4*)g_cand + base;
    float4* __restrict__ op = (float4*)out + base;

    float4 h = ((const float4*)g_hin)[((size_t)(b * NC + ch) * D_) / 4 + d4];
#pragma unroll 4
    for (int l = 0; l < CL; l++) {
        float4 gv = gp[(size_t)l * (D_ / 4)];
        float4 cv = cp[(size_t)l * (D_ / 4)];
        h.x = gv.x * h.x + (1.f - gv.x) * cv.x;
        h.y = gv.y * h.y + (1.f - gv.y) * cv.y;
        h.z = gv.z * h.z + (1.f - gv.z) * cv.z;
        h.w = gv.w * h.w + (1.f - gv.w) * cv.w;
        op[(size_t)l * (D_ / 4)] = h;
    }
}

// ---------------------------------------------------------------------------
extern "C" void kernel_launch(void* const* d_in, const int* in_sizes, int n_in,
                              void* d_out, int out_size)
{
    const float* x      = (const float*)d_in[0];
    const float* hidden = (const float*)d_in[1];
    const float* Wg     = (const float*)d_in[2];
    const float* bg     = (const float*)d_in[3];
    const float* Wh     = (const float*)d_in[4];
    const float* bh     = (const float*)d_in[5];
    float* out = (float*)d_out;

    // Unconditional + idempotent (no statics allowed in kernel_launch).
    cudaFuncSetAttribute(gemm_act_fp16,
                         cudaFuncAttributeMaxDynamicSharedMemorySize, DYN_SMEM);

    __half* xh = nullptr, *wh = nullptr;
    cudaGetSymbolAddress((void**)&xh, g_xh);
    cudaGetSymbolAddress((void**)&wh, g_wh);

    // P0: fp32 -> fp16
    to_half<<<(M_ * D_ / 8 + 255) / 256, 256>>>(x, xh, M_ * D_ / 8);
    to_half<<<(D_ * D_ / 8 + 255) / 256, 256>>>(Wg, wh, D_ * D_ / 8);
    to_half<<<(D_ * D_ / 8 + 255) / 256, 256>>>(Wh, wh + (size_t)D_ * D_, D_ * D_ / 8);

    // K1: dual GEMM (z = gate/cand)
    gemm_act_fp16<<<dim3(Nsz / BN, M_ / BM, 2), 256, DYN_SMEM>>>(bg, bh);

    // K2..K4: scan
    scan_phase1<<<dim3(NC, B_), 256>>>();
    scan_phase2<<<(B_ * D_) / 256, 256>>>(hidden);
    scan_phase3<<<dim3(NC, B_), 256>>>(out);
}